// round 7
// baseline (speedup 1.0000x reference)
#include <cuda_runtime.h>
#include <cstdint>

#define INW    128
#define OUTW   128
#define BATCHN 128

// grid = 128 (one block per output o), block = 512 = 16 warps.
// Pipeline: issue x LDG.128s -> WHT on tid<256 (hides x latency) -> sign pack/store
// -> barrier -> SWAR + register-table/shuffle main loop (R4 datapath).
__global__ void __launch_bounds__(512, 1) fused_kernel(
    const float* __restrict__ x,
    const float* __restrict__ weight,
    const float* __restrict__ bias,
    const float* __restrict__ means,
    const int*   __restrict__ mask,
    float*       __restrict__ out)
{
    __shared__ float         sW[INW * 33];      // [i]: 16 (lvl0) + 16 (lvl1), row pad 33
    __shared__ unsigned      sSBw[INW * 33];    // [i][b0g] word = 4 sign bytes, row pad 33 words
    __shared__ int4          sIdx[INW];         // 4 taps per table
    __shared__ float         red[16 * BATCHN];  // per-warp partials [w][b]

    const int tid  = threadIdx.x;
    const int lane = tid & 31;
    const int w    = tid >> 5;       // warp 0..15
    const int o    = blockIdx.x;

    const float a0 = fabsf(means[0]);
    const float a1 = fabsf(means[1]);

    // ---------- Phase A: issue x loads (2 tiles of 4i x 4b per thread) ----------
    // tile T = j*512 + tid ; grp = T>>5 (warp-uniform), lane = T&31
    // i4  = (lane&7) + 8*(grp&3)      (i-group of 4 consecutive i)
    // b0g = 4*(grp>>2) + (lane>>3)    (batch-group of 4 consecutive b)
    float4 xa[2][4];
    int i4v[2], bgv[2];
    #pragma unroll
    for (int j = 0; j < 2; j++) {
        const int grp = (j * 512 + tid) >> 5;
        const int i4  = (lane & 7) + 8 * (grp & 3);
        const int bg  = 4 * (grp >> 2) + (lane >> 3);
        i4v[j] = i4; bgv[j] = bg;
        #pragma unroll
        for (int kb = 0; kb < 4; kb++)
            xa[j][kb] = ((const float4*)x)[(bg * 4 + kb) * (INW / 4) + i4];  // coalesced
    }

    // ---------- Phase B: WHT on tid<256 (x loads in flight underneath) ----------
    if (tid < 256) {
        const int t = tid & 127;
        const int l = tid >> 7;
        float f[16];
        const float4* wp = (const float4*)(weight + (size_t)(o * INW + t) * 16);
        #pragma unroll
        for (int q = 0; q < 4; q++) {
            float4 v = wp[q];
            f[q*4+0] = v.x; f[q*4+1] = v.y; f[q*4+2] = v.z; f[q*4+3] = v.w;
        }
        #pragma unroll
        for (int s = 1; s < 16; s <<= 1)
            #pragma unroll
            for (int i2 = 0; i2 < 16; i2++)
                if (!(i2 & s)) { float u = f[i2], v = f[i2 ^ s]; f[i2] = u + v; f[i2 ^ s] = u - v; }

        const float a = (l == 0) ? a0 : a1;
        float pw[5];
        pw[0] = 1.0f / 16.0f;
        pw[1] = pw[0] * a; pw[2] = pw[1] * a; pw[3] = pw[2] * a; pw[4] = pw[3] * a;
        #pragma unroll
        for (int i2 = 0; i2 < 16; i2++) f[i2] *= pw[__popc(i2)];
        #pragma unroll
        for (int s = 1; s < 16; s <<= 1)
            #pragma unroll
            for (int i2 = 0; i2 < 16; i2++)
                if (!(i2 & s)) { float u = f[i2], v = f[i2 ^ s]; f[i2] = u + v; f[i2 ^ s] = u - v; }

        float* dst = &sW[t * 33 + l * 16];
        #pragma unroll
        for (int i2 = 0; i2 < 16; i2++) dst[i2] = f[i2];
    } else if (tid < 384) {
        sIdx[tid - 256] = ((const int4*)mask)[o * INW + (tid - 256)];
    }

    // ---------- Phase C: pack sign bytes, store words (conflict-free banks) ----------
    #pragma unroll
    for (int j = 0; j < 2; j++) {
        const int i4 = i4v[j], bg = bgv[j];
        #pragma unroll
        for (int k = 0; k < 4; k++) {           // element k of each float4 -> i = 4*i4+k
            unsigned word = 0;
            #pragma unroll
            for (int kb = 0; kb < 4; kb++) {
                float v = (k == 0) ? xa[j][kb].x : (k == 1) ? xa[j][kb].y
                        : (k == 2) ? xa[j][kb].z : xa[j][kb].w;
                bool  s0  = (v >= 0.0f);
                float thr = s0 ? a0 : -a0;
                bool  s1  = (v >= thr);
                unsigned byte = (s0 ? 1u : 0u) | (s1 ? 16u : 0u);
                word |= byte << (kb * 8);
            }
            sSBw[(i4 * 4 + k) * 33 + bg] = word;  // bank 4*(lane&7)+(lane>>3)+k : conflict-free
        }
    }
    __syncthreads();

    // ---------- main loop: warp w -> i in [w*8, w*8+8), lane -> batches 4*lane..+3 ----------
    float acc0 = 0.0f, acc1 = 0.0f, acc2 = 0.0f, acc3 = 0.0f;

    #pragma unroll
    for (int k = 0; k < 8; k++) {
        const int i = w * 8 + k;
        const int4 id = sIdx[i];                         // uniform: broadcast LDS.128
        const float tbl = sW[i * 33 + lane];             // bank (i+lane)%32: conflict-free

        unsigned v0 = sSBw[id.x * 33 + lane];            // banks = lane: conflict-free
        unsigned v1 = sSBw[id.y * 33 + lane];
        unsigned v2 = sSBw[id.z * 33 + lane];
        unsigned v3 = sSBw[id.w * 33 + lane];

        // byte m of VC = (g0 | g1<<4) for batch 4*lane+m
        unsigned VC = (v0 & 0x11111111u)
                    + ((v1 & 0x11111111u) << 1)
                    + ((v2 & 0x11111111u) << 2)
                    + ((v3 & 0x11111111u) << 3);

        unsigned c0 = VC & 0xffu;
        unsigned c1 = (VC >> 8) & 0xffu;
        unsigned c2 = (VC >> 16) & 0xffu;
        unsigned c3 = VC >> 24;

        acc0 += __shfl_sync(0xffffffffu, tbl, c0 & 15u)
              + __shfl_sync(0xffffffffu, tbl, (c0 >> 4) + 16u);
        acc1 += __shfl_sync(0xffffffffu, tbl, c1 & 15u)
              + __shfl_sync(0xffffffffu, tbl, (c1 >> 4) + 16u);
        acc2 += __shfl_sync(0xffffffffu, tbl, c2 & 15u)
              + __shfl_sync(0xffffffffu, tbl, (c2 >> 4) + 16u);
        acc3 += __shfl_sync(0xffffffffu, tbl, c3 & 15u)
              + __shfl_sync(0xffffffffu, tbl, (c3 >> 4) + 16u);
    }

    // partials: red[w][b]
    ((float4*)red)[w * 32 + lane] = make_float4(acc0, acc1, acc2, acc3);
    __syncthreads();

    // ---------- final reduce over 16 warps, add bias, store ----------
    if (tid < 128) {
        const int b = tid;
        float tot = bias[o];
        #pragma unroll
        for (int ww = 0; ww < 16; ww++) tot += red[ww * BATCHN + b];  // bank b%32: conflict-free
        out[b * OUTW + o] = tot;
    }
}

// ---------------------------------------------------------------------------
extern "C" void kernel_launch(void* const* d_in, const int* in_sizes, int n_in,
                              void* d_out, int out_size) {
    const float* x      = (const float*)d_in[0];
    const float* weight = (const float*)d_in[1];
    const float* bias   = (const float*)d_in[2];
    const float* means  = (const float*)d_in[3];
    const int*   mask   = (const int*)  d_in[4];
    float* out = (float*)d_out;

    fused_kernel<<<OUTW, 512>>>(x, weight, bias, means, mask, out);
}

// round 8
// speedup vs baseline: 1.0295x; 1.0295x over previous
#include <cuda_runtime.h>
#include <cstdint>

#define INW    128
#define OUTW   128
#define BATCHN 128

// grid = 128 (one block per output o), block = 512 = 16 warps.
// Pipeline: issue x LDG.128s -> WHT on tid<256 (hides x latency) -> sign pack/store
// -> barrier -> SWAR + register-table/shuffle main loop.
__global__ void __launch_bounds__(512, 1) fused_kernel(
    const float* __restrict__ x,
    const float* __restrict__ weight,
    const float* __restrict__ bias,
    const float* __restrict__ means,
    const int*   __restrict__ mask,
    float*       __restrict__ out)
{
    __shared__ float         sW[INW * 33];      // [i]: 16 (lvl0) + 16 (lvl1), row pad 33
    __shared__ unsigned      sSBw[INW * 33];    // [i][bg] word = 4 sign bytes, row pad 33 words
    __shared__ int4          sIdx[INW];         // 4 taps per table
    __shared__ float         red[16 * BATCHN];  // per-warp partials [w][b]

    const int tid  = threadIdx.x;
    const int lane = tid & 31;
    const int w    = tid >> 5;       // warp 0..15
    const int o    = blockIdx.x;

    const float a0 = fabsf(means[0]);
    const float a1 = fabsf(means[1]);
    const float bias_o = bias[o];    // prefetch (hides LDG under everything else)

    // ---------- Phase A: issue x loads (2 tiles of 4i x 4b per thread) ----------
    // tile T = j*512 + tid ; grp = T>>5 (warp-uniform)
    // i4  = (lane&7) + 8*(grp&3)      (group of 4 consecutive i)
    // bg  = 4*(grp>>2) + (lane>>3)    (group of 4 consecutive b)
    float4 xa[2][4];
    int i4v[2], bgv[2];
    #pragma unroll
    for (int j = 0; j < 2; j++) {
        const int grp = (j * 512 + tid) >> 5;
        const int i4  = (lane & 7) + 8 * (grp & 3);
        const int bg  = 4 * (grp >> 2) + (lane >> 3);
        i4v[j] = i4; bgv[j] = bg;
        #pragma unroll
        for (int kb = 0; kb < 4; kb++)
            xa[j][kb] = ((const float4*)x)[(bg * 4 + kb) * (INW / 4) + i4];  // coalesced
    }

    // ---------- Phase B: WHT on tid<256 (x loads in flight underneath) ----------
    if (tid < 256) {
        const int t = tid & 127;
        const int l = tid >> 7;
        float f[16];
        const float4* wp = (const float4*)(weight + (size_t)(o * INW + t) * 16);
        #pragma unroll
        for (int q = 0; q < 4; q++) {
            float4 v = wp[q];
            f[q*4+0] = v.x; f[q*4+1] = v.y; f[q*4+2] = v.z; f[q*4+3] = v.w;
        }
        #pragma unroll
        for (int s = 1; s < 16; s <<= 1)
            #pragma unroll
            for (int i2 = 0; i2 < 16; i2++)
                if (!(i2 & s)) { float u = f[i2], v = f[i2 ^ s]; f[i2] = u + v; f[i2 ^ s] = u - v; }

        const float a = (l == 0) ? a0 : a1;
        float pw[5];
        pw[0] = 1.0f / 16.0f;
        pw[1] = pw[0] * a; pw[2] = pw[1] * a; pw[3] = pw[2] * a; pw[4] = pw[3] * a;
        #pragma unroll
        for (int i2 = 0; i2 < 16; i2++) f[i2] *= pw[__popc(i2)];
        #pragma unroll
        for (int s = 1; s < 16; s <<= 1)
            #pragma unroll
            for (int i2 = 0; i2 < 16; i2++)
                if (!(i2 & s)) { float u = f[i2], v = f[i2 ^ s]; f[i2] = u + v; f[i2 ^ s] = u - v; }

        float* dst = &sW[t * 33 + l * 16];
        #pragma unroll
        for (int i2 = 0; i2 < 16; i2++) dst[i2] = f[i2];
    } else if (tid < 384) {
        sIdx[tid - 256] = ((const int4*)mask)[o * INW + (tid - 256)];
    }

    // ---------- Phase C: pack sign bytes, store words (conflict-free banks) ----------
    #pragma unroll
    for (int j = 0; j < 2; j++) {
        const int i4 = i4v[j], bg = bgv[j];
        #pragma unroll
        for (int k = 0; k < 4; k++) {           // element k of each float4 -> i = 4*i4+k
            unsigned word = 0;
            #pragma unroll
            for (int kb = 0; kb < 4; kb++) {
                float v = (k == 0) ? xa[j][kb].x : (k == 1) ? xa[j][kb].y
                        : (k == 2) ? xa[j][kb].z : xa[j][kb].w;
                bool  s0  = (v >= 0.0f);
                float thr = s0 ? a0 : -a0;
                bool  s1  = (v >= thr);
                unsigned byte = (s0 ? 1u : 0u) | (s1 ? 16u : 0u);
                word |= byte << (kb * 8);
            }
            sSBw[(i4 * 4 + k) * 33 + bg] = word;  // bank 4*(lane&7)+(lane>>3)+k : conflict-free
        }
    }
    __syncthreads();

    // ---------- main loop: warp w -> i in [w*8, w*8+8), lane -> batches 4*lane..+3 ----------
    float acc0 = 0.0f, acc1 = 0.0f, acc2 = 0.0f, acc3 = 0.0f;

    #pragma unroll
    for (int k = 0; k < 8; k++) {
        const int i = w * 8 + k;
        const int4 id = sIdx[i];                         // uniform: broadcast LDS.128
        const float tbl = sW[i * 33 + lane];             // bank (i+lane)%32: conflict-free

        unsigned v0 = sSBw[id.x * 33 + lane];            // banks = lane: conflict-free
        unsigned v1 = sSBw[id.y * 33 + lane];
        unsigned v2 = sSBw[id.z * 33 + lane];
        unsigned v3 = sSBw[id.w * 33 + lane];

        // byte m of VC = (g0 | g1<<4) for batch 4*lane+m
        unsigned VC = (v0 & 0x11111111u)
                    + ((v1 & 0x11111111u) << 1)
                    + ((v2 & 0x11111111u) << 2)
                    + ((v3 & 0x11111111u) << 3);

        // pre-split nibbles: lo bytes = g0, hi bytes = g1+16 (shuffle-ready)
        unsigned lo = VC & 0x0f0f0f0fu;
        unsigned hi = ((VC >> 4) & 0x0f0f0f0fu) | 0x10101010u;

        acc0 += __shfl_sync(0xffffffffu, tbl, __byte_perm(lo, 0, 0x4440))
              + __shfl_sync(0xffffffffu, tbl, __byte_perm(hi, 0, 0x4440));
        acc1 += __shfl_sync(0xffffffffu, tbl, __byte_perm(lo, 0, 0x4441))
              + __shfl_sync(0xffffffffu, tbl, __byte_perm(hi, 0, 0x4441));
        acc2 += __shfl_sync(0xffffffffu, tbl, __byte_perm(lo, 0, 0x4442))
              + __shfl_sync(0xffffffffu, tbl, __byte_perm(hi, 0, 0x4442));
        acc3 += __shfl_sync(0xffffffffu, tbl, __byte_perm(lo, 0, 0x4443))
              + __shfl_sync(0xffffffffu, tbl, __byte_perm(hi, 0, 0x4443));
    }

    // partials: red[w][b]
    ((float4*)red)[w * 32 + lane] = make_float4(acc0, acc1, acc2, acc3);
    __syncthreads();

    // ---------- final reduce over 16 warps, add bias, store ----------
    if (tid < 128) {
        const int b = tid;
        float tot = bias_o;
        #pragma unroll
        for (int ww = 0; ww < 16; ww++) tot += red[ww * BATCHN + b];  // bank b%32: conflict-free
        out[b * OUTW + o] = tot;
    }
}

// ---------------------------------------------------------------------------
extern "C" void kernel_launch(void* const* d_in, const int* in_sizes, int n_in,
                              void* d_out, int out_size) {
    const float* x      = (const float*)d_in[0];
    const float* weight = (const float*)d_in[1];
    const float* bias   = (const float*)d_in[2];
    const float* means  = (const float*)d_in[3];
    const int*   mask   = (const int*)  d_in[4];
    float* out = (float*)d_out;

    fused_kernel<<<OUTW, 512>>>(x, weight, bias, means, mask, out);
}